// round 13
// baseline (speedup 1.0000x reference)
#include <cuda_runtime.h>
#include <cuda_fp16.h>
#include <cstdint>

#define D_  2048
#define H_  1408
#define HS_ 2816
#define E_  8
#define N_  4096
#define NK_ (2*N_)

typedef __half fp16;

constexpr size_t EDH = (size_t)E_ * D_ * H_;
constexpr size_t DHS = (size_t)D_ * HS_;
constexpr size_t XSZ = (size_t)N_ * D_;

// -------- static scratch (no runtime allocation allowed) --------
__device__ fp16 g_wg[EDH];            // transposed [E][H][D]
__device__ fp16 g_wu[EDH];
__device__ fp16 g_wd[EDH];            // transposed [E][D][H]
__device__ fp16 g_sg[DHS];            // transposed [HS][D]
__device__ fp16 g_su[DHS];
__device__ fp16 g_sd[DHS];            // transposed [D][HS]
__device__ fp16 g_x[XSZ];             // [N][D]
__device__ fp16 g_hs[(size_t)N_ * HS_];    // shared-expert hidden
__device__ fp16 g_hr[(size_t)NK_ * H_];    // routed hidden
__device__ int   g_perm[NK_];
__device__ float g_pgate[NK_];
__device__ int   g_counts[E_];
__device__ int   g_offsets[E_ + 1];
__device__ int   g_gidx[NK_];
__device__ float g_gval[NK_];

// -------- helpers --------
__device__ __forceinline__ void cpa(uint32_t d, const void* s) {
    asm volatile("cp.async.cg.shared.global [%0], [%1], 16;" :: "r"(d), "l"(s));
}
__device__ __forceinline__ void ldmx4(uint32_t* r, uint32_t a) {
    asm volatile("ldmatrix.sync.aligned.m8n8.x4.shared.b16 {%0,%1,%2,%3}, [%4];"
                 : "=r"(r[0]), "=r"(r[1]), "=r"(r[2]), "=r"(r[3]) : "r"(a));
}
__device__ __forceinline__ void mma16816(float* c, const uint32_t* a, const uint32_t* b) {
    asm volatile(
        "mma.sync.aligned.m16n8k16.row.col.f32.f16.f16.f32 "
        "{%0,%1,%2,%3},{%4,%5,%6,%7},{%8,%9},{%0,%1,%2,%3};"
        : "+f"(c[0]), "+f"(c[1]), "+f"(c[2]), "+f"(c[3])
        : "r"(a[0]), "r"(a[1]), "r"(a[2]), "r"(a[3]), "r"(b[0]), "r"(b[1]));
}

// -------- conversion kernels --------
__global__ void tconvh(const float* __restrict__ src, fp16* __restrict__ dst,
                       int R, int C) {
    __shared__ float t[64][33];
    size_t zo = (size_t)blockIdx.z * R * C;
    src += zo; dst += zo;
    int c0 = blockIdx.x * 32, r0 = blockIdx.y * 64;
    int tx = threadIdx.x, ty = threadIdx.y;
#pragma unroll
    for (int i = 0; i < 8; i++)
        t[ty + 8 * i][tx] = src[(size_t)(r0 + ty + 8 * i) * C + c0 + tx];
    __syncthreads();
#pragma unroll
    for (int i = 0; i < 4; i++) {
        int cx = ty + 8 * i;
        float v0 = t[2 * tx][cx];
        float v1 = t[2 * tx + 1][cx];
        *(__half2*)(dst + (size_t)(c0 + cx) * R + r0 + 2 * tx) =
            __halves2half2(__float2half_rn(v0), __float2half_rn(v1));
    }
}

__global__ void xconv(const float* __restrict__ x) {
    size_t i = (size_t)blockIdx.x * blockDim.x + threadIdx.x;
    float4 v = ((const float4*)x)[i];
    __half2* p = (__half2*)(g_x + 4 * i);
    p[0] = __halves2half2(__float2half_rn(v.x), __float2half_rn(v.y));
    p[1] = __halves2half2(__float2half_rn(v.z), __float2half_rn(v.w));
}

// -------- router + list build (proven) --------
__global__ void router_kernel(const float* __restrict__ x, const float* __restrict__ rw) {
    int gw = (blockIdx.x * blockDim.x + threadIdx.x) >> 5;
    int lane = threadIdx.x & 31;
    if (gw >= N_) return;
    const float* xr = x + (size_t)gw * D_;
    float acc[E_];
#pragma unroll
    for (int e = 0; e < E_; e++) acc[e] = 0.f;
    for (int d = lane * 4; d < D_; d += 128) {
        float4 xv = *(const float4*)(xr + d);
#pragma unroll
        for (int e = 0; e < E_; e++) {
            float4 wv = *(const float4*)(rw + e * D_ + d);
            acc[e] += xv.x * wv.x + xv.y * wv.y + xv.z * wv.z + xv.w * wv.w;
        }
    }
#pragma unroll
    for (int e = 0; e < E_; e++) {
#pragma unroll
        for (int o = 16; o > 0; o >>= 1)
            acc[e] += __shfl_down_sync(0xffffffffu, acc[e], o);
    }
    if (lane == 0) {
        float mx = acc[0];
#pragma unroll
        for (int e = 1; e < E_; e++) mx = fmaxf(mx, acc[e]);
        float p[E_], s = 0.f;
#pragma unroll
        for (int e = 0; e < E_; e++) { p[e] = expf(acc[e] - mx); s += p[e]; }
        int i1 = 0;
#pragma unroll
        for (int e = 1; e < E_; e++) if (p[e] > p[i1]) i1 = e;
        int i2 = (i1 == 0) ? 1 : 0;
#pragma unroll
        for (int e = 0; e < E_; e++) if (e != i1 && p[e] > p[i2]) i2 = e;
        float g1 = p[i1] / s, g2 = p[i2] / s;
        float den = g1 + g2 + 1e-20f;
        g_gidx[2 * gw]     = i1; g_gval[2 * gw]     = g1 / den;
        g_gidx[2 * gw + 1] = i2; g_gval[2 * gw + 1] = g2 / den;
    }
}

__global__ void build_lists_kernel() {
    __shared__ int scnt[E_];
    __shared__ int soff[E_];
    int wid = threadIdx.x >> 5, lane = threadIdx.x & 31;
    if (wid < E_) {
        int c = 0;
        for (int base = 0; base < NK_; base += 32) {
            int flag = (g_gidx[base + lane] == wid);
            c += __popc(__ballot_sync(0xffffffffu, flag));
        }
        if (lane == 0) scnt[wid] = c;
    }
    __syncthreads();
    if (threadIdx.x == 0) {
        int s = 0;
        for (int e = 0; e < E_; e++) {
            soff[e] = s; g_offsets[e] = s; g_counts[e] = scnt[e]; s += scnt[e];
        }
        g_offsets[E_] = s;
    }
    __syncthreads();
    if (wid < E_) {
        int pos = soff[wid];
        for (int base = 0; base < NK_; base += 32) {
            int t = base + lane;
            int flag = (g_gidx[t] == wid);
            unsigned m = __ballot_sync(0xffffffffu, flag);
            if (flag) {
                int off = __popc(m & ((1u << lane) - 1u));
                g_perm[pos + off]  = t >> 1;
                g_pgate[pos + off] = g_gval[t];
            }
            pos += __popc(m);
        }
    }
}

// ---------------------------------------------------------------------------
// Fused gate/up GEMM + SiLU -> hbuf. BM=128 BN=64 BK=64, 256 threads
// (8 warps: 4m x 2n, warp tile 32x32), fp16 x fp16 -> fp32, 2 CTAs/SM.
// 3-stage cp.async pipeline, one sync per iter, B frags double-buffered.
// Rows 144B (128B data + 16B pad). A tile 128*144=18432, B tiles 64*144=9216.
// Stage: A 0, G 18432, U 27648. Stage stride 36864.
// ---------------------------------------------------------------------------
#define STG_GU 36864
template<bool ROUTED>
__global__ void __launch_bounds__(256, 2)
gateup_mma(fp16* __restrict__ hbuf, int Nn) {
    int e    = ROUTED ? blockIdx.z : 0;
    int M    = ROUTED ? g_counts[e] : N_;
    int base = ROUTED ? g_offsets[e] : 0;
    int m0 = blockIdx.x * 128;
    if (m0 >= M) return;
    int n0 = blockIdx.y * 64;

    size_t eoff = ROUTED ? (size_t)e * D_ * H_ : 0;
    const fp16* Bg = (ROUTED ? g_wg : g_sg) + eoff;
    const fp16* Bu = (ROUTED ? g_wu : g_su) + eoff;

    extern __shared__ char smem[];
    __shared__ int stok[128];
    int tid = threadIdx.x;
    if (tid < 128) {
        int r = m0 + tid; if (r > M - 1) r = M - 1;
        stok[tid] = ROUTED ? g_perm[base + r] : r;
    }
    __syncthreads();

    // A loader: thread -> row rA (0..127), 4 chunks of 16B at cqA
    int rA  = tid >> 1;
    int cqA = (tid & 1) * 64;
    // B loader: thread -> row rB (0..63), 2 chunks of 16B at cqB
    int rB  = tid >> 2;
    int cqB = (tid & 3) * 32;
    const char* pA = (const char*)(g_x + (size_t)stok[rA] * D_) + cqA;
    const char* pG = (const char*)(Bg + (size_t)(n0 + rB) * D_) + cqB;
    const char* pU = (const char*)(Bu + (size_t)(n0 + rB) * D_) + cqB;

    uint32_t sb = (uint32_t)__cvta_generic_to_shared(smem);
    uint32_t drA = sb + rA * 144 + cqA;
    uint32_t drG = sb + 18432 + rB * 144 + cqB;
    uint32_t drU = sb + 27648 + rB * 144 + cqB;

    auto issue = [&](int stage, int kt) {
        uint32_t so = stage * STG_GU;
        size_t ko = (size_t)kt * 128;
#pragma unroll
        for (int i = 0; i < 4; i++)
            cpa(drA + so + i * 16, pA + ko + i * 16);
#pragma unroll
        for (int i = 0; i < 2; i++) {
            cpa(drG + so + i * 16, pG + ko + i * 16);
            cpa(drU + so + i * 16, pU + ko + i * 16);
        }
        asm volatile("cp.async.commit_group;");
    };

    int lane = tid & 31, wid = tid >> 5;
    int wm = (wid & 3) * 32;          // 4 m-warps
    int wn = (wid >> 2) * 32;         // 2 n-warps
    int grp = lane >> 3, lr = lane & 7;
    uint32_t aoff[2], boff[2];
#pragma unroll
    for (int mf = 0; mf < 2; mf++)
        aoff[mf] = (uint32_t)((wm + mf * 16 + (grp & 1) * 8 + lr) * 144 + (grp >> 1) * 16);
#pragma unroll
    for (int nf2 = 0; nf2 < 2; nf2++)
        boff[nf2] = (uint32_t)((wn + nf2 * 16 + (grp >> 1) * 8 + lr) * 144 + (grp & 1) * 16);

    float cg[2][4][4], cu[2][4][4];
#pragma unroll
    for (int a = 0; a < 2; a++)
#pragma unroll
    for (int b = 0; b < 4; b++)
#pragma unroll
    for (int c = 0; c < 4; c++) { cg[a][b][c] = 0.f; cu[a][b][c] = 0.f; }

    const int KI = D_ / 64;   // 32
    issue(0, 0);
    issue(1, 1);
    int cur = 0;
    for (int kt = 0; kt < KI; kt++) {
        if (kt + 1 < KI) {
            asm volatile("cp.async.wait_group 1;");
        } else {
            asm volatile("cp.async.wait_group 0;");
        }
        __syncthreads();
        if (kt + 2 < KI) {
            int nstage = cur + 2; if (nstage >= 3) nstage -= 3;
            issue(nstage, kt + 2);
        }
        uint32_t st = sb + cur * STG_GU;

        uint32_t bgf[2][2][4], buf_[2][2][4];
#pragma unroll
        for (int nf2 = 0; nf2 < 2; nf2++) {
            ldmx4(bgf[0][nf2], st + 18432 + boff[nf2]);
            ldmx4(buf_[0][nf2], st + 27648 + boff[nf2]);
        }
#pragma unroll
        for (int ks = 0; ks < 4; ks++) {
            int cb = ks & 1;
            if (ks < 3) {
                uint32_t kb = (ks + 1) * 32;
#pragma unroll
                for (int nf2 = 0; nf2 < 2; nf2++) {
                    ldmx4(bgf[cb ^ 1][nf2], st + 18432 + boff[nf2] + kb);
                    ldmx4(buf_[cb ^ 1][nf2], st + 27648 + boff[nf2] + kb);
                }
            }
            uint32_t ah[2][4];
            uint32_t kb = ks * 32;
#pragma unroll
            for (int mf = 0; mf < 2; mf++)
                ldmx4(ah[mf], st + aoff[mf] + kb);
#pragma unroll
            for (int mf = 0; mf < 2; mf++)
#pragma unroll
            for (int nf2 = 0; nf2 < 2; nf2++)
#pragma unroll
            for (int j = 0; j < 2; j++) {
                int nf = nf2 * 2 + j;
                mma16816(cg[mf][nf], ah[mf], &bgf[cb][nf2][2 * j]);
                mma16816(cu[mf][nf], ah[mf], &buf_[cb][nf2][2 * j]);
            }
        }
        if (++cur == 3) cur = 0;
    }

#pragma unroll
    for (int mf = 0; mf < 2; mf++)
#pragma unroll
    for (int nf = 0; nf < 4; nf++) {
        int r = m0 + wm + mf * 16 + (lane >> 2);
        int c = n0 + wn + nf * 8 + (lane & 3) * 2;
#pragma unroll
        for (int h = 0; h < 2; h++) {
            int rr = r + h * 8;
            if (rr < M) {
                float gv0 = cg[mf][nf][2 * h],     gv1 = cg[mf][nf][2 * h + 1];
                float uv0 = cu[mf][nf][2 * h],     uv1 = cu[mf][nf][2 * h + 1];
                float h0 = gv0 / (1.f + expf(-gv0)) * uv0;
                float h1 = gv1 / (1.f + expf(-gv1)) * uv1;
                size_t o = (size_t)(base + rr) * Nn + c;
                *(__half2*)(hbuf + o) =
                    __halves2half2(__float2half_rn(h0), __float2half_rn(h1));
            }
        }
    }
}

// ---------------------------------------------------------------------------
// Down projection GEMM. BM=128 BN=64 BK=64, 256 threads, 2 CTAs/SM,
// 3-stage pipeline, B frags double-buffered. Rows 144B.
// Stage: A 0 (18432), B 18432 (9216). Stage stride 27648.
// ---------------------------------------------------------------------------
#define STG_DN 27648
template<bool ROUTED>
__global__ void __launch_bounds__(256, 2)
down_mma(const fp16* __restrict__ hbuf, float* __restrict__ out, int Kk) {
    int e    = ROUTED ? blockIdx.z : 0;
    int M    = ROUTED ? g_counts[e] : N_;
    int base = ROUTED ? g_offsets[e] : 0;
    int m0 = blockIdx.x * 128;
    if (m0 >= M) return;
    int n0 = blockIdx.y * 64;

    size_t eoff = ROUTED ? (size_t)e * D_ * H_ : 0;
    const fp16* Bw = (ROUTED ? g_wd : g_sd) + eoff;

    extern __shared__ char smem[];
    int tid = threadIdx.x;
    int rA  = tid >> 1;
    int cqA = (tid & 1) * 64;
    int rB  = tid >> 2;
    int cqB = (tid & 3) * 32;
    int ra = m0 + rA; if (ra > M - 1) ra = M - 1;
    const char* pA = (const char*)(hbuf + (size_t)(base + ra) * Kk) + cqA;
    const char* pB = (const char*)(Bw + (size_t)(n0 + rB) * Kk) + cqB;

    uint32_t sb = (uint32_t)__cvta_generic_to_shared(smem);
    uint32_t drA = sb + rA * 144 + cqA;
    uint32_t drB = sb + 18432 + rB * 144 + cqB;

    auto issue = [&](int stage, int kt) {
        uint32_t so = stage * STG_DN;
        size_t ko = (size_t)kt * 128;
#pragma unroll
        for (int i = 0; i < 4; i++)
            cpa(drA + so + i * 16, pA + ko + i * 16);
#pragma unroll
        for (int i = 0; i < 2; i++)
            cpa(drB + so + i * 16, pB + ko + i * 16);
        asm volatile("cp.async.commit_group;");
    };

    int lane = tid & 31, wid = tid >> 5;
    int wm = (wid & 3) * 32;
    int wn = (wid >> 2) * 32;
    int grp = lane >> 3, lr = lane & 7;
    uint32_t aoff[2], boff[2];
#pragma unroll
    for (int mf = 0; mf < 2; mf++)
        aoff[mf] = (uint32_t)((wm + mf * 16 + (grp & 1) * 8 + lr) * 144 + (grp >> 1) * 16);
#pragma unroll
    for (int nf2 = 0; nf2 < 2; nf2++)
        boff[nf2] = (uint32_t)((wn + nf2 * 16 + (grp >> 1) * 8 + lr) * 144 + (grp & 1) * 16);

    float cd[2][4][4];
#pragma unroll
    for (int a = 0; a < 2; a++)
#pragma unroll
    for (int b = 0; b < 4; b++)
#pragma unroll
    for (int c = 0; c < 4; c++) cd[a][b][c] = 0.f;

    const int KI = Kk / 64;
    issue(0, 0);
    issue(1, 1);
    int cur = 0;
    for (int kt = 0; kt < KI; kt++) {
        if (kt + 1 < KI) {
            asm volatile("cp.async.wait_group 1;");
        } else {
            asm volatile("cp.async.wait_group 0;");
        }
        __syncthreads();
        if (kt + 2 < KI) {
            int nstage = cur + 2; if (nstage >= 3) nstage -= 3;
            issue(nstage, kt + 2);
        }
        uint32_t st = sb + cur * STG_DN;

        uint32_t bwf[2][2][4];
#pragma unroll
        for (int nf2 = 0; nf2 < 2; nf2++)
            ldmx4(bwf[0][nf2], st + 18432 + boff[nf2]);
#pragma unroll
        for (int ks = 0; ks < 4; ks++) {
            int cb = ks & 1;
            if (ks < 3) {
                uint32_t kb = (ks + 1) * 32;
#pragma unroll
                for (int nf2 = 0; nf2 < 2; nf2++)
                    ldmx4(bwf[cb ^ 1][nf2], st + 18432 + boff[nf2] + kb);
            }
            uint32_t ah[2][4];
            uint32_t kb = ks * 32;
#pragma unroll
            for (int mf = 0; mf < 2; mf++)
                ldmx4(ah[mf], st + aoff[mf] + kb);
#pragma unroll
            for (int mf = 0; mf < 2; mf++)
#pragma unroll
            for (int nf2 = 0; nf2 < 2; nf2++)
#pragma unroll
            for (int j = 0; j < 2; j++) {
                int nf = nf2 * 2 + j;
                mma16816(cd[mf][nf], ah[mf], &bwf[cb][nf2][2 * j]);
            }
        }
        if (++cur == 3) cur = 0;
    }

#pragma unroll
    for (int mf = 0; mf < 2; mf++)
#pragma unroll
    for (int nf = 0; nf < 4; nf++) {
        int r = m0 + wm + mf * 16 + (lane >> 2);
        int c = n0 + wn + nf * 8 + (lane & 3) * 2;
#pragma unroll
        for (int h = 0; h < 2; h++) {
            int rr = r + h * 8;
            if (rr < M) {
                float v0 = cd[mf][nf][2 * h], v1 = cd[mf][nf][2 * h + 1];
                if (ROUTED) {
                    int p = base + rr;
                    float gt = g_pgate[p];
                    float* op = out + (size_t)g_perm[p] * D_ + c;
                    atomicAdd(op,     v0 * gt);
                    atomicAdd(op + 1, v1 * gt);
                } else {
                    *(float2*)(out + (size_t)rr * D_ + c) = make_float2(v0, v1);
                }
            }
        }
    }
}

// ---------------------------------------------------------------------------
extern "C" void kernel_launch(void* const* d_in, const int* in_sizes, int n_in,
                              void* d_out, int out_size) {
    const float* x  = (const float*)d_in[0];
    const float* rw = (const float*)d_in[1];
    const float* wg = (const float*)d_in[2];
    const float* wu = (const float*)d_in[3];
    const float* wd = (const float*)d_in[4];
    const float* sg = (const float*)d_in[5];
    const float* su = (const float*)d_in[6];
    const float* sd = (const float*)d_in[7];
    float* out = (float*)d_out;

    const int SMEM_GU = 3 * STG_GU;   // 110592 (2 CTAs/SM)
    const int SMEM_DN = 3 * STG_DN;   // 82944  (2 CTAs/SM)
    cudaFuncSetAttribute(gateup_mma<false>, cudaFuncAttributeMaxDynamicSharedMemorySize, SMEM_GU);
    cudaFuncSetAttribute(gateup_mma<true>,  cudaFuncAttributeMaxDynamicSharedMemorySize, SMEM_GU);
    cudaFuncSetAttribute(down_mma<false>,   cudaFuncAttributeMaxDynamicSharedMemorySize, SMEM_DN);
    cudaFuncSetAttribute(down_mma<true>,    cudaFuncAttributeMaxDynamicSharedMemorySize, SMEM_DN);

    fp16 *pwg, *pwu, *pwd, *psg, *psu, *psd, *phs, *phr;
    cudaGetSymbolAddress((void**)&pwg, g_wg);
    cudaGetSymbolAddress((void**)&pwu, g_wu);
    cudaGetSymbolAddress((void**)&pwd, g_wd);
    cudaGetSymbolAddress((void**)&psg, g_sg);
    cudaGetSymbolAddress((void**)&psu, g_su);
    cudaGetSymbolAddress((void**)&psd, g_sd);
    cudaGetSymbolAddress((void**)&phs, g_hs);
    cudaGetSymbolAddress((void**)&phr, g_hr);

    cudaStream_t s1;
    cudaStreamCreateWithFlags(&s1, cudaStreamNonBlocking);
    cudaEvent_t eF, eX, eS, eJ;
    cudaEventCreateWithFlags(&eF, cudaEventDisableTiming);
    cudaEventCreateWithFlags(&eX, cudaEventDisableTiming);
    cudaEventCreateWithFlags(&eS, cudaEventDisableTiming);
    cudaEventCreateWithFlags(&eJ, cudaEventDisableTiming);

    dim3 tb(32, 8);

    cudaEventRecord(eF, 0);
    cudaStreamWaitEvent(s1, eF, 0);

    // ---- legacy: shared-expert chain ----
    xconv<<<(N_ * D_ / 4) / 256, 256>>>(x);
    cudaEventRecord(eX, 0);                                  // g_x ready
    tconvh<<<dim3(HS_ / 32, D_ / 64, 1), tb>>>(sg, psg, D_, HS_);
    tconvh<<<dim3(HS_ / 32, D_ / 64, 1), tb>>>(su, psu, D_, HS_);
    gateup_mma<false><<<dim3(N_ / 128, HS_ / 64, 1), 256, SMEM_GU>>>(phs, HS_);
    tconvh<<<dim3(D_ / 32, HS_ / 64, 1), tb>>>(sd, psd, HS_, D_);
    down_mma<false><<<dim3(N_ / 128, D_ / 64, 1), 256, SMEM_DN>>>(phs, out, HS_);
    cudaEventRecord(eS, 0);                                  // out initialized

    // ---- s1: router + routed chain ----
    router_kernel<<<N_ / 8, 256, 0, s1>>>(x, rw);
    build_lists_kernel<<<1, 256, 0, s1>>>();
    tconvh<<<dim3(H_ / 32, D_ / 64, E_), tb, 0, s1>>>(wg, pwg, D_, H_);
    tconvh<<<dim3(H_ / 32, D_ / 64, E_), tb, 0, s1>>>(wu, pwu, D_, H_);
    cudaStreamWaitEvent(s1, eX, 0);                          // need g_x
    gateup_mma<true><<<dim3(N_ / 128, H_ / 64, E_), 256, SMEM_GU, s1>>>(phr, H_);
    tconvh<<<dim3(D_ / 32, H_ / 64, E_), tb, 0, s1>>>(wd, pwd, H_, D_);
    cudaStreamWaitEvent(s1, eS, 0);                          // need out init
    down_mma<true><<<dim3(N_ / 128, D_ / 64, E_), 256, SMEM_DN, s1>>>(phr, out, H_);
    cudaEventRecord(eJ, s1);

    cudaStreamWaitEvent(0, eJ, 0);
}

// round 14
// speedup vs baseline: 1.1486x; 1.1486x over previous
#include <cuda_runtime.h>
#include <cuda_fp16.h>
#include <cstdint>

#define D_  2048
#define H_  1408
#define HS_ 2816
#define E_  8
#define N_  4096
#define NK_ (2*N_)

typedef __half fp16;

constexpr size_t EDH = (size_t)E_ * D_ * H_;
constexpr size_t DHS = (size_t)D_ * HS_;
constexpr size_t XSZ = (size_t)N_ * D_;

// -------- static scratch (no runtime allocation allowed) --------
__device__ fp16 g_wg[EDH];            // transposed [E][H][D]
__device__ fp16 g_wu[EDH];
__device__ fp16 g_wd[EDH];            // transposed [E][D][H]
__device__ fp16 g_sg[DHS];            // transposed [HS][D]
__device__ fp16 g_su[DHS];
__device__ fp16 g_sd[DHS];            // transposed [D][HS]
__device__ fp16 g_x[XSZ];             // [N][D]
__device__ fp16 g_hs[(size_t)N_ * HS_];    // shared-expert hidden
__device__ fp16 g_hr[(size_t)NK_ * H_];    // routed hidden
__device__ float g_ro[(size_t)N_ * D_];    // routed output accumulator
__device__ int   g_perm[NK_];
__device__ float g_pgate[NK_];
__device__ int   g_counts[E_];
__device__ int   g_offsets[E_ + 1];
__device__ int   g_gidx[NK_];
__device__ float g_gval[NK_];

// -------- helpers --------
__device__ __forceinline__ void cpa(uint32_t d, const void* s) {
    asm volatile("cp.async.cg.shared.global [%0], [%1], 16;" :: "r"(d), "l"(s));
}
__device__ __forceinline__ void ldmx4(uint32_t* r, uint32_t a) {
    asm volatile("ldmatrix.sync.aligned.m8n8.x4.shared.b16 {%0,%1,%2,%3}, [%4];"
                 : "=r"(r[0]), "=r"(r[1]), "=r"(r[2]), "=r"(r[3]) : "r"(a));
}
__device__ __forceinline__ void mma16816(float* c, const uint32_t* a, const uint32_t* b) {
    asm volatile(
        "mma.sync.aligned.m16n8k16.row.col.f32.f16.f16.f32 "
        "{%0,%1,%2,%3},{%4,%5,%6,%7},{%8,%9},{%0,%1,%2,%3};"
        : "+f"(c[0]), "+f"(c[1]), "+f"(c[2]), "+f"(c[3])
        : "r"(a[0]), "r"(a[1]), "r"(a[2]), "r"(a[3]), "r"(b[0]), "r"(b[1]));
}

// -------- conversion / utility kernels --------
__global__ void tconvh(const float* __restrict__ src, fp16* __restrict__ dst,
                       int R, int C) {
    __shared__ float t[64][33];
    size_t zo = (size_t)blockIdx.z * R * C;
    src += zo; dst += zo;
    int c0 = blockIdx.x * 32, r0 = blockIdx.y * 64;
    int tx = threadIdx.x, ty = threadIdx.y;
#pragma unroll
    for (int i = 0; i < 8; i++)
        t[ty + 8 * i][tx] = src[(size_t)(r0 + ty + 8 * i) * C + c0 + tx];
    __syncthreads();
#pragma unroll
    for (int i = 0; i < 4; i++) {
        int cx = ty + 8 * i;
        float v0 = t[2 * tx][cx];
        float v1 = t[2 * tx + 1][cx];
        *(__half2*)(dst + (size_t)(c0 + cx) * R + r0 + 2 * tx) =
            __halves2half2(__float2half_rn(v0), __float2half_rn(v1));
    }
}

__global__ void xconv(const float* __restrict__ x) {
    size_t i = (size_t)blockIdx.x * blockDim.x + threadIdx.x;
    float4 v = ((const float4*)x)[i];
    __half2* p = (__half2*)(g_x + 4 * i);
    p[0] = __halves2half2(__float2half_rn(v.x), __float2half_rn(v.y));
    p[1] = __halves2half2(__float2half_rn(v.z), __float2half_rn(v.w));
}

__global__ void zero_ro() {
    size_t i = (size_t)blockIdx.x * blockDim.x + threadIdx.x;
    ((float4*)g_ro)[i] = make_float4(0.f, 0.f, 0.f, 0.f);
}

__global__ void merge_out(float* __restrict__ out) {
    size_t i = (size_t)blockIdx.x * blockDim.x + threadIdx.x;
    float4 a = ((const float4*)out)[i];
    float4 b = ((const float4*)g_ro)[i];
    ((float4*)out)[i] = make_float4(a.x + b.x, a.y + b.y, a.z + b.z, a.w + b.w);
}

// -------- router + list build (proven) --------
__global__ void router_kernel(const float* __restrict__ x, const float* __restrict__ rw) {
    int gw = (blockIdx.x * blockDim.x + threadIdx.x) >> 5;
    int lane = threadIdx.x & 31;
    if (gw >= N_) return;
    const float* xr = x + (size_t)gw * D_;
    float acc[E_];
#pragma unroll
    for (int e = 0; e < E_; e++) acc[e] = 0.f;
    for (int d = lane * 4; d < D_; d += 128) {
        float4 xv = *(const float4*)(xr + d);
#pragma unroll
        for (int e = 0; e < E_; e++) {
            float4 wv = *(const float4*)(rw + e * D_ + d);
            acc[e] += xv.x * wv.x + xv.y * wv.y + xv.z * wv.z + xv.w * wv.w;
        }
    }
#pragma unroll
    for (int e = 0; e < E_; e++) {
#pragma unroll
        for (int o = 16; o > 0; o >>= 1)
            acc[e] += __shfl_down_sync(0xffffffffu, acc[e], o);
    }
    if (lane == 0) {
        float mx = acc[0];
#pragma unroll
        for (int e = 1; e < E_; e++) mx = fmaxf(mx, acc[e]);
        float p[E_], s = 0.f;
#pragma unroll
        for (int e = 0; e < E_; e++) { p[e] = expf(acc[e] - mx); s += p[e]; }
        int i1 = 0;
#pragma unroll
        for (int e = 1; e < E_; e++) if (p[e] > p[i1]) i1 = e;
        int i2 = (i1 == 0) ? 1 : 0;
#pragma unroll
        for (int e = 0; e < E_; e++) if (e != i1 && p[e] > p[i2]) i2 = e;
        float g1 = p[i1] / s, g2 = p[i2] / s;
        float den = g1 + g2 + 1e-20f;
        g_gidx[2 * gw]     = i1; g_gval[2 * gw]     = g1 / den;
        g_gidx[2 * gw + 1] = i2; g_gval[2 * gw + 1] = g2 / den;
    }
}

__global__ void build_lists_kernel() {
    __shared__ int scnt[E_];
    __shared__ int soff[E_];
    int wid = threadIdx.x >> 5, lane = threadIdx.x & 31;
    if (wid < E_) {
        int c = 0;
        for (int base = 0; base < NK_; base += 32) {
            int flag = (g_gidx[base + lane] == wid);
            c += __popc(__ballot_sync(0xffffffffu, flag));
        }
        if (lane == 0) scnt[wid] = c;
    }
    __syncthreads();
    if (threadIdx.x == 0) {
        int s = 0;
        for (int e = 0; e < E_; e++) {
            soff[e] = s; g_offsets[e] = s; g_counts[e] = scnt[e]; s += scnt[e];
        }
        g_offsets[E_] = s;
    }
    __syncthreads();
    if (wid < E_) {
        int pos = soff[wid];
        for (int base = 0; base < NK_; base += 32) {
            int t = base + lane;
            int flag = (g_gidx[t] == wid);
            unsigned m = __ballot_sync(0xffffffffu, flag);
            if (flag) {
                int off = __popc(m & ((1u << lane) - 1u));
                g_perm[pos + off]  = t >> 1;
                g_pgate[pos + off] = g_gval[t];
            }
            pos += __popc(m);
        }
    }
}

// ---------------------------------------------------------------------------
// Fused gate/up GEMM + SiLU -> hbuf. BM=128 BN=128 BK=64, 512 threads
// (16 warps, 4m x 4n, warp tile 32x32), fp16 x fp16 -> fp32.
// 3-stage cp.async pipeline, one sync per iter; B frags double-buffered.
// Rows 144B (128B data + 16B pad). Tile 128*144 = 18432B.
// Stage: A 0, G 18432, U 36864. Stage stride 55296.
// ---------------------------------------------------------------------------
#define STG_GU 55296
template<bool ROUTED>
__global__ void __launch_bounds__(512)
gateup_mma(fp16* __restrict__ hbuf, int Nn) {
    int e    = ROUTED ? blockIdx.z : 0;
    int M    = ROUTED ? g_counts[e] : N_;
    int base = ROUTED ? g_offsets[e] : 0;
    int m0 = blockIdx.x * 128;
    if (m0 >= M) return;
    int n0 = blockIdx.y * 128;

    size_t eoff = ROUTED ? (size_t)e * D_ * H_ : 0;
    const fp16* Bg = (ROUTED ? g_wg : g_sg) + eoff;
    const fp16* Bu = (ROUTED ? g_wu : g_su) + eoff;

    extern __shared__ char smem[];
    __shared__ int stok[128];
    int tid = threadIdx.x;
    if (tid < 128) {
        int r = m0 + tid; if (r > M - 1) r = M - 1;
        stok[tid] = ROUTED ? g_perm[base + r] : r;
    }
    __syncthreads();

    int row = tid >> 2;
    int kq  = (tid & 3) * 16;
    const char* pA = (const char*)(g_x + (size_t)stok[row] * D_) + kq;
    const char* pG = (const char*)(Bg + (size_t)(n0 + row) * D_) + kq;
    const char* pU = (const char*)(Bu + (size_t)(n0 + row) * D_) + kq;

    uint32_t sb = (uint32_t)__cvta_generic_to_shared(smem);
    uint32_t dr = sb + row * 144 + kq;

    auto issue = [&](int stage, int kt) {
        uint32_t so = stage * STG_GU;
        size_t ko = (size_t)kt * 128;
        cpa(dr + so,              pA + ko);
        cpa(dr + so + 64,         pA + ko + 64);
        cpa(dr + so + 18432,      pG + ko);
        cpa(dr + so + 18432 + 64, pG + ko + 64);
        cpa(dr + so + 36864,      pU + ko);
        cpa(dr + so + 36864 + 64, pU + ko + 64);
        asm volatile("cp.async.commit_group;");
    };

    int lane = tid & 31, wid = tid >> 5;
    int wm = (wid & 3) * 32;
    int wn = (wid >> 2) * 32;
    int grp = lane >> 3, lr = lane & 7;
    uint32_t aoff[2], boff[2];
#pragma unroll
    for (int mf = 0; mf < 2; mf++)
        aoff[mf] = (uint32_t)((wm + mf * 16 + (grp & 1) * 8 + lr) * 144 + (grp >> 1) * 16);
#pragma unroll
    for (int nf2 = 0; nf2 < 2; nf2++)
        boff[nf2] = (uint32_t)((wn + nf2 * 16 + (grp >> 1) * 8 + lr) * 144 + (grp & 1) * 16);

    float cg[2][4][4], cu[2][4][4];
#pragma unroll
    for (int a = 0; a < 2; a++)
#pragma unroll
    for (int b = 0; b < 4; b++)
#pragma unroll
    for (int c = 0; c < 4; c++) { cg[a][b][c] = 0.f; cu[a][b][c] = 0.f; }

    const int KI = D_ / 64;   // 32
    issue(0, 0);
    issue(1, 1);
    int cur = 0;
    for (int kt = 0; kt < KI; kt++) {
        if (kt + 1 < KI) {
            asm volatile("cp.async.wait_group 1;");
        } else {
            asm volatile("cp.async.wait_group 0;");
        }
        __syncthreads();
        if (kt + 2 < KI) {
            int nstage = cur + 2; if (nstage >= 3) nstage -= 3;
            issue(nstage, kt + 2);
        }
        uint32_t st = sb + cur * STG_GU;

        uint32_t bgf[2][2][4], buf_[2][2][4];
#pragma unroll
        for (int nf2 = 0; nf2 < 2; nf2++) {
            ldmx4(bgf[0][nf2], st + 18432 + boff[nf2]);
            ldmx4(buf_[0][nf2], st + 36864 + boff[nf2]);
        }
#pragma unroll
        for (int ks = 0; ks < 4; ks++) {
            int cb = ks & 1;
            if (ks < 3) {
                uint32_t kb = (ks + 1) * 32;
#pragma unroll
                for (int nf2 = 0; nf2 < 2; nf2++) {
                    ldmx4(bgf[cb ^ 1][nf2], st + 18432 + boff[nf2] + kb);
                    ldmx4(buf_[cb ^ 1][nf2], st + 36864 + boff[nf2] + kb);
                }
            }
            uint32_t ah[2][4];
            uint32_t kb = ks * 32;
#pragma unroll
            for (int mf = 0; mf < 2; mf++)
                ldmx4(ah[mf], st + aoff[mf] + kb);
#pragma unroll
            for (int mf = 0; mf < 2; mf++)
#pragma unroll
            for (int nf2 = 0; nf2 < 2; nf2++)
#pragma unroll
            for (int j = 0; j < 2; j++) {
                int nf = nf2 * 2 + j;
                mma16816(cg[mf][nf], ah[mf], &bgf[cb][nf2][2 * j]);
                mma16816(cu[mf][nf], ah[mf], &buf_[cb][nf2][2 * j]);
            }
        }
        if (++cur == 3) cur = 0;
    }

#pragma unroll
    for (int mf = 0; mf < 2; mf++)
#pragma unroll
    for (int nf = 0; nf < 4; nf++) {
        int r = m0 + wm + mf * 16 + (lane >> 2);
        int c = n0 + wn + nf * 8 + (lane & 3) * 2;
#pragma unroll
        for (int h = 0; h < 2; h++) {
            int rr = r + h * 8;
            if (rr < M) {
                float gv0 = cg[mf][nf][2 * h],     gv1 = cg[mf][nf][2 * h + 1];
                float uv0 = cu[mf][nf][2 * h],     uv1 = cu[mf][nf][2 * h + 1];
                float h0 = gv0 / (1.f + expf(-gv0)) * uv0;
                float h1 = gv1 / (1.f + expf(-gv1)) * uv1;
                size_t o = (size_t)(base + rr) * Nn + c;
                *(__half2*)(hbuf + o) =
                    __halves2half2(__float2half_rn(h0), __float2half_rn(h1));
            }
        }
    }
}

// ---------------------------------------------------------------------------
// Down projection GEMM. BM=128 BN=128 BK=64, 512 threads, 3-stage pipeline,
// B fragments double-buffered. Rows 144B. Stage: A 0, B 18432; stride 36864.
// ROUTED: atomicAdd into g_ro (zero-initialized); shared: plain store to out.
// ---------------------------------------------------------------------------
#define STG_DN 36864
template<bool ROUTED>
__global__ void __launch_bounds__(512)
down_mma(const fp16* __restrict__ hbuf, float* __restrict__ out, int Kk) {
    int e    = ROUTED ? blockIdx.z : 0;
    int M    = ROUTED ? g_counts[e] : N_;
    int base = ROUTED ? g_offsets[e] : 0;
    int m0 = blockIdx.x * 128;
    if (m0 >= M) return;
    int n0 = blockIdx.y * 128;

    size_t eoff = ROUTED ? (size_t)e * D_ * H_ : 0;
    const fp16* Bw = (ROUTED ? g_wd : g_sd) + eoff;

    extern __shared__ char smem[];
    int tid = threadIdx.x;
    int row = tid >> 2;
    int kq  = (tid & 3) * 16;
    int ra = m0 + row; if (ra > M - 1) ra = M - 1;
    const char* pA = (const char*)(hbuf + (size_t)(base + ra) * Kk) + kq;
    const char* pB = (const char*)(Bw + (size_t)(n0 + row) * Kk) + kq;

    uint32_t sb = (uint32_t)__cvta_generic_to_shared(smem);
    uint32_t dr = sb + row * 144 + kq;

    auto issue = [&](int stage, int kt) {
        uint32_t so = stage * STG_DN;
        size_t ko = (size_t)kt * 128;
        cpa(dr + so,              pA + ko);
        cpa(dr + so + 64,         pA + ko + 64);
        cpa(dr + so + 18432,      pB + ko);
        cpa(dr + so + 18432 + 64, pB + ko + 64);
        asm volatile("cp.async.commit_group;");
    };

    int lane = tid & 31, wid = tid >> 5;
    int wm = (wid & 3) * 32;
    int wn = (wid >> 2) * 32;
    int grp = lane >> 3, lr = lane & 7;
    uint32_t aoff[2], boff[2];
#pragma unroll
    for (int mf = 0; mf < 2; mf++)
        aoff[mf] = (uint32_t)((wm + mf * 16 + (grp & 1) * 8 + lr) * 144 + (grp >> 1) * 16);
#pragma unroll
    for (int nf2 = 0; nf2 < 2; nf2++)
        boff[nf2] = (uint32_t)((wn + nf2 * 16 + (grp >> 1) * 8 + lr) * 144 + (grp & 1) * 16);

    float cd[2][4][4];
#pragma unroll
    for (int a = 0; a < 2; a++)
#pragma unroll
    for (int b = 0; b < 4; b++)
#pragma unroll
    for (int c = 0; c < 4; c++) cd[a][b][c] = 0.f;

    const int KI = Kk / 64;
    issue(0, 0);
    issue(1, 1);
    int cur = 0;
    for (int kt = 0; kt < KI; kt++) {
        if (kt + 1 < KI) {
            asm volatile("cp.async.wait_group 1;");
        } else {
            asm volatile("cp.async.wait_group 0;");
        }
        __syncthreads();
        if (kt + 2 < KI) {
            int nstage = cur + 2; if (nstage >= 3) nstage -= 3;
            issue(nstage, kt + 2);
        }
        uint32_t st = sb + cur * STG_DN;

        uint32_t bwf[2][2][4];
#pragma unroll
        for (int nf2 = 0; nf2 < 2; nf2++)
            ldmx4(bwf[0][nf2], st + 18432 + boff[nf2]);
#pragma unroll
        for (int ks = 0; ks < 4; ks++) {
            int cb = ks & 1;
            if (ks < 3) {
                uint32_t kb = (ks + 1) * 32;
#pragma unroll
                for (int nf2 = 0; nf2 < 2; nf2++)
                    ldmx4(bwf[cb ^ 1][nf2], st + 18432 + boff[nf2] + kb);
            }
            uint32_t ah[2][4];
            uint32_t kb = ks * 32;
#pragma unroll
            for (int mf = 0; mf < 2; mf++)
                ldmx4(ah[mf], st + aoff[mf] + kb);
#pragma unroll
            for (int mf = 0; mf < 2; mf++)
#pragma unroll
            for (int nf2 = 0; nf2 < 2; nf2++)
#pragma unroll
            for (int j = 0; j < 2; j++) {
                int nf = nf2 * 2 + j;
                mma16816(cd[mf][nf], ah[mf], &bwf[cb][nf2][2 * j]);
            }
        }
        if (++cur == 3) cur = 0;
    }

#pragma unroll
    for (int mf = 0; mf < 2; mf++)
#pragma unroll
    for (int nf = 0; nf < 4; nf++) {
        int r = m0 + wm + mf * 16 + (lane >> 2);
        int c = n0 + wn + nf * 8 + (lane & 3) * 2;
#pragma unroll
        for (int h = 0; h < 2; h++) {
            int rr = r + h * 8;
            if (rr < M) {
                float v0 = cd[mf][nf][2 * h], v1 = cd[mf][nf][2 * h + 1];
                if (ROUTED) {
                    int p = base + rr;
                    float gt = g_pgate[p];
                    float* op = g_ro + (size_t)g_perm[p] * D_ + c;
                    atomicAdd(op,     v0 * gt);
                    atomicAdd(op + 1, v1 * gt);
                } else {
                    *(float2*)(out + (size_t)rr * D_ + c) = make_float2(v0, v1);
                }
            }
        }
    }
}

// ---------------------------------------------------------------------------
extern "C" void kernel_launch(void* const* d_in, const int* in_sizes, int n_in,
                              void* d_out, int out_size) {
    const float* x  = (const float*)d_in[0];
    const float* rw = (const float*)d_in[1];
    const float* wg = (const float*)d_in[2];
    const float* wu = (const float*)d_in[3];
    const float* wd = (const float*)d_in[4];
    const float* sg = (const float*)d_in[5];
    const float* su = (const float*)d_in[6];
    const float* sd = (const float*)d_in[7];
    float* out = (float*)d_out;

    const int SMEM_GU = 3 * STG_GU;   // 165888
    const int SMEM_DN = 3 * STG_DN;   // 110592
    cudaFuncSetAttribute(gateup_mma<false>, cudaFuncAttributeMaxDynamicSharedMemorySize, SMEM_GU);
    cudaFuncSetAttribute(gateup_mma<true>,  cudaFuncAttributeMaxDynamicSharedMemorySize, SMEM_GU);
    cudaFuncSetAttribute(down_mma<false>,   cudaFuncAttributeMaxDynamicSharedMemorySize, SMEM_DN);
    cudaFuncSetAttribute(down_mma<true>,    cudaFuncAttributeMaxDynamicSharedMemorySize, SMEM_DN);

    fp16 *pwg, *pwu, *pwd, *psg, *psu, *psd, *phs, *phr;
    cudaGetSymbolAddress((void**)&pwg, g_wg);
    cudaGetSymbolAddress((void**)&pwu, g_wu);
    cudaGetSymbolAddress((void**)&pwd, g_wd);
    cudaGetSymbolAddress((void**)&psg, g_sg);
    cudaGetSymbolAddress((void**)&psu, g_su);
    cudaGetSymbolAddress((void**)&psd, g_sd);
    cudaGetSymbolAddress((void**)&phs, g_hs);
    cudaGetSymbolAddress((void**)&phr, g_hr);

    cudaStream_t s1;
    cudaStreamCreateWithFlags(&s1, cudaStreamNonBlocking);
    cudaEvent_t eF, eX, eJ;
    cudaEventCreateWithFlags(&eF, cudaEventDisableTiming);
    cudaEventCreateWithFlags(&eX, cudaEventDisableTiming);
    cudaEventCreateWithFlags(&eJ, cudaEventDisableTiming);

    dim3 tb(32, 8);

    cudaEventRecord(eF, 0);
    cudaStreamWaitEvent(s1, eF, 0);

    // ---- legacy: shared-expert chain (independent) ----
    xconv<<<(N_ * D_ / 4) / 256, 256>>>(x);
    cudaEventRecord(eX, 0);                                  // g_x ready
    tconvh<<<dim3(HS_ / 32, D_ / 64, 1), tb>>>(sg, psg, D_, HS_);
    tconvh<<<dim3(HS_ / 32, D_ / 64, 1), tb>>>(su, psu, D_, HS_);
    gateup_mma<false><<<dim3(N_ / 128, HS_ / 128, 1), 512, SMEM_GU>>>(phs, HS_);
    tconvh<<<dim3(D_ / 32, HS_ / 64, 1), tb>>>(sd, psd, HS_, D_);
    down_mma<false><<<dim3(N_ / 128, D_ / 128, 1), 512, SMEM_DN>>>(phs, out, HS_);

    // ---- s1: router + routed chain (independent, accumulates into g_ro) ----
    zero_ro<<<(N_ * D_ / 4) / 256, 256, 0, s1>>>();
    router_kernel<<<N_ / 8, 256, 0, s1>>>(x, rw);
    build_lists_kernel<<<1, 256, 0, s1>>>();
    tconvh<<<dim3(H_ / 32, D_ / 64, E_), tb, 0, s1>>>(wg, pwg, D_, H_);
    tconvh<<<dim3(H_ / 32, D_ / 64, E_), tb, 0, s1>>>(wu, pwu, D_, H_);
    cudaStreamWaitEvent(s1, eX, 0);                          // need g_x
    gateup_mma<true><<<dim3(N_ / 128, H_ / 128, E_), 512, SMEM_GU, s1>>>(phr, H_);
    tconvh<<<dim3(D_ / 32, H_ / 64, E_), tb, 0, s1>>>(wd, pwd, H_, D_);
    down_mma<true><<<dim3(N_ / 128, D_ / 128, E_), 512, SMEM_DN, s1>>>(phr, out, H_);
    cudaEventRecord(eJ, s1);

    // join + merge
    cudaStreamWaitEvent(0, eJ, 0);
    merge_out<<<(N_ * D_ / 4) / 256, 256>>>(out);
}